// round 2
// baseline (speedup 1.0000x reference)
#include <cuda_runtime.h>
#include <math.h>

#define D    256
#define L    512
#define NU   64
#define PAD  260        // padded SMEM row stride (floats): 1040B, 16B-aligned, bank-skewed

// word kernel decomposition: 8 batch groups x 16 hidden slices = 128 CTAs
#define GB   8
#define UPG  8          // utterances per group
#define GH   16
#define HPS  16         // hidden units per slice
#define RPS  48         // gate rows per slice (3*HPS)
#define WT   384        // threads per CTA (RPS * UPG)

// ---------------- device scratch (static; no allocations) ----------------
__device__ float g_h_hist[(size_t)L * NU * D];   // word-GRU hidden history (33.5 MB)
__device__ float g_utt[NU * D];                  // utterance vectors after word attn-pool
__device__ int   g_cnt[GB];                      // per-group monotonic barrier counters

// ---------------- packed fp32x2 helpers ----------------
__device__ __forceinline__ unsigned long long ffma2(unsigned long long a,
                                                    unsigned long long b,
                                                    unsigned long long c) {
    unsigned long long d;
    asm("fma.rn.f32x2 %0, %1, %2, %3;" : "=l"(d) : "l"(a), "l"(b), "l"(c));
    return d;
}
__device__ __forceinline__ float2 unpk2(unsigned long long v) {
    float2 r;
    asm("mov.b64 {%0, %1}, %2;" : "=f"(r.x), "=f"(r.y) : "l"(v));
    return r;
}
__device__ __forceinline__ int ld_acquire(const int* p) {
    int v;
    asm volatile("ld.acquire.gpu.b32 %0, [%1];" : "=r"(v) : "l"(p) : "memory");
    return v;
}
__device__ __forceinline__ float sigmoidf_(float x) { return 1.f / (1.f + expf(-x)); }

// gate row -> global weight row (gate order r, z, n)
__device__ __forceinline__ int gate_row(int i0, int lr) {
    return (lr < 16) ? (i0 + lr)
         : (lr < 32) ? (256 + i0 + (lr - 16))
                     : (512 + i0 + (lr - 32));
}

// fused dual dot over 256 floats: (wa.xa) and (wb.xb), SMEM operands, 16B aligned
__device__ __forceinline__ void dot_dual(const float* __restrict__ wa, const float* __restrict__ xa,
                                         const float* __restrict__ wb, const float* __restrict__ xb,
                                         float& ra, float& rb) {
    const ulonglong2* WA = (const ulonglong2*)wa;
    const ulonglong2* XA = (const ulonglong2*)xa;
    const ulonglong2* WB = (const ulonglong2*)wb;
    const ulonglong2* XB = (const ulonglong2*)xb;
    unsigned long long a0 = 0ull, a1 = 0ull, a2 = 0ull, a3 = 0ull;
    unsigned long long b0 = 0ull, b1 = 0ull, b2 = 0ull, b3 = 0ull;
#pragma unroll
    for (int k = 0; k < 64; k += 2) {
        ulonglong2 w0 = WA[k], w1 = WA[k + 1];
        ulonglong2 x0 = XA[k], x1 = XA[k + 1];
        a0 = ffma2(w0.x, x0.x, a0);
        a1 = ffma2(w0.y, x0.y, a1);
        a2 = ffma2(w1.x, x1.x, a2);
        a3 = ffma2(w1.y, x1.y, a3);
        ulonglong2 v0 = WB[k], v1 = WB[k + 1];
        ulonglong2 y0 = XB[k], y1 = XB[k + 1];
        b0 = ffma2(v0.x, y0.x, b0);
        b1 = ffma2(v0.y, y0.y, b1);
        b2 = ffma2(v1.x, y1.x, b2);
        b3 = ffma2(v1.y, y1.y, b3);
    }
    float2 f0 = unpk2(a0), f1 = unpk2(a1), f2 = unpk2(a2), f3 = unpk2(a3);
    ra = ((f0.x + f0.y) + (f1.x + f1.y)) + ((f2.x + f2.y) + (f3.x + f3.y));
    f0 = unpk2(b0); f1 = unpk2(b1); f2 = unpk2(b2); f3 = unpk2(b3);
    rb = ((f0.x + f0.y) + (f1.x + f1.y)) + ((f2.x + f2.y) + (f3.x + f3.y));
}

// ---------------- reset: zero group counters each launch ----------------
__global__ void reset_kernel() {
    if (threadIdx.x < GB) g_cnt[threadIdx.x] = 0;
}

// ---------------- word GRU persistent kernel ----------------
// SMEM layout (floats):
//  s_wih[48][260] @0        s_whh[48][260] @12480
//  s_x[2][8][260] @24960    s_h[8][260]    @29120
//  s_gih[384]     @31200    s_ghh[384]     @31584
//  s_bih[48]      @31968    s_bhh[48]      @32016   => 32064 floats = 128256 B
#define OFF_WIH 0
#define OFF_WHH 12480
#define OFF_X   24960
#define OFF_H   29120
#define OFF_GIH 31200
#define OFF_GHH 31584
#define OFF_BIH 31968
#define OFF_BHH 32016
#define WORD_SMEM_BYTES (32064 * 4)

__global__ void __launch_bounds__(WT, 1)
word_kernel(const int* __restrict__ tokens, const float* __restrict__ embed,
            const float* __restrict__ Wih, const float* __restrict__ Whh,
            const float* __restrict__ bih, const float* __restrict__ bhh) {
    extern __shared__ float sm[];
    float* s_wih = sm + OFF_WIH;
    float* s_whh = sm + OFF_WHH;
    float* s_x   = sm + OFF_X;
    float* s_h   = sm + OFF_H;
    float* s_gih = sm + OFF_GIH;
    float* s_ghh = sm + OFF_GHH;
    float* s_bih = sm + OFF_BIH;
    float* s_bhh = sm + OFF_BHH;

    const int g   = blockIdx.x >> 4;   // batch group
    const int sl  = blockIdx.x & 15;   // hidden slice
    const int i0  = sl * HPS;
    const int b0  = g * UPG;
    const int tid = threadIdx.x;
    const int u   = tid & 7;           // utterance within group
    const int lr  = tid >> 3;          // gate row within slice (0..47)
    const bool have2 = (tid < 128);    // second strip for 512-float4 copies

    // ---- prologue: load resident weight slices ----
    for (int idx = tid; idx < RPS * D; idx += WT) {
        int r = idx >> 8, k = idx & 255;
        int grow = gate_row(i0, r);
        s_wih[r * PAD + k] = Wih[grow * D + k];
        s_whh[r * PAD + k] = Whh[grow * D + k];
    }
    if (tid < RPS) {
        int grow = gate_row(i0, tid);
        s_bih[tid] = bih[grow];
        s_bhh[tid] = bhh[grow];
    }
    // emb for t=0 into buffer 0; zero h
    for (int idx = tid; idx < UPG * 64; idx += WT) {
        int uu = idx >> 6, k4 = idx & 63;
        int tok = tokens[(b0 + uu) * L + 0];
        ((float4*)(s_x + uu * PAD))[k4] = ((const float4*)(embed + (size_t)tok * D))[k4];
    }
    for (int idx = tid; idx < UPG * 64; idx += WT) {
        int uu = idx >> 6, k4 = idx & 63;
        ((float4*)(s_h + uu * PAD))[k4] = make_float4(0.f, 0.f, 0.f, 0.f);
    }
    __syncthreads();

    for (int t = 0; t < L; ++t) {
        const int buf = t & 1;

        // 1) prefetch emb rows for t+1 into registers (hides gather latency)
        float4 pf0 = make_float4(0.f, 0.f, 0.f, 0.f);
        float4 pf1 = make_float4(0.f, 0.f, 0.f, 0.f);
        if (t + 1 < L) {
            int idx = tid, uu = idx >> 6, k4 = idx & 63;
            int tok = tokens[(b0 + uu) * L + (t + 1)];
            pf0 = ((const float4*)(embed + (size_t)tok * D))[k4];
            if (have2) {
                idx = tid + WT; uu = idx >> 6; k4 = idx & 63;
                tok = tokens[(b0 + uu) * L + (t + 1)];
                pf1 = ((const float4*)(embed + (size_t)tok * D))[k4];
            }
        }

        // 2) wait for h_{t-1} from the group's 16 slices; stage into SMEM
        if (t > 0) {
            if (tid == 0) {
                while (ld_acquire(&g_cnt[g]) < 16 * t) { }
            }
            __syncthreads();
            const float4* src = (const float4*)(g_h_hist + (size_t)(t - 1) * NU * D + (size_t)b0 * D);
            {
                int idx = tid, uu = idx >> 6, k4 = idx & 63;
                ((float4*)(s_h + uu * PAD))[k4] = src[idx];
                if (have2) {
                    idx = tid + WT; uu = idx >> 6; k4 = idx & 63;
                    ((float4*)(s_h + uu * PAD))[k4] = src[idx];
                }
            }
        }

        // 3) store prefetched emb (t+1) into the other buffer
        if (t + 1 < L) {
            int idx = tid, uu = idx >> 6, k4 = idx & 63;
            ((float4*)(s_x + (buf ^ 1) * 2080 + uu * PAD))[k4] = pf0;
            if (have2) {
                idx = tid + WT; uu = idx >> 6; k4 = idx & 63;
                ((float4*)(s_x + (buf ^ 1) * 2080 + uu * PAD))[k4] = pf1;
            }
        }
        __syncthreads();

        // 4) fused dual GEMV: gate preactivations from emb (ih) and h_{t-1} (hh)
        float aih, ahh;
        dot_dual(s_wih + lr * PAD, s_x + buf * 2080 + u * PAD,
                 s_whh + lr * PAD, s_h + u * PAD, aih, ahh);
        s_gih[tid] = aih + s_bih[lr];
        s_ghh[tid] = ahh + s_bhh[lr];
        __syncthreads();

        // 5) gates + hidden update + publish
        if (tid < 128) {
            int ii = tid >> 3, uu = tid & 7;
            float xr = s_gih[ii * 8 + uu],        hr = s_ghh[ii * 8 + uu];
            float xz = s_gih[(16 + ii) * 8 + uu], hz = s_ghh[(16 + ii) * 8 + uu];
            float xn = s_gih[(32 + ii) * 8 + uu], hn = s_ghh[(32 + ii) * 8 + uu];
            float r = sigmoidf_(xr + hr);
            float z = sigmoidf_(xz + hz);
            float n = tanhf(xn + r * hn);
            float hprev = s_h[uu * PAD + i0 + ii];
            float hnew = (1.f - z) * n + z * hprev;
            g_h_hist[(size_t)t * NU * D + (size_t)(b0 + uu) * D + (i0 + ii)] = hnew;
        }
        __syncthreads();
        if (tid == 0) {
            __threadfence();            // release h_t writes
            atomicAdd(&g_cnt[g], 1);
        }
    }
}

// ---------------- word-level attention pool: h_hist -> g_utt ----------------
__global__ void __launch_bounds__(256, 1)
pool_kernel(const float* __restrict__ ua_w) {
    __shared__ float s_w[D];
    __shared__ float s_l[L];
    __shared__ float s_red[32];
    const int b = blockIdx.x, tid = threadIdx.x;
    const int lane = tid & 31, wp = tid >> 5;   // 8 warps

    s_w[tid] = ua_w[tid];
    __syncthreads();

    const float* base = g_h_hist + (size_t)b * D;  // + t*NU*D per step
    // logits: each warp handles 64 timesteps
    for (int tt = 0; tt < 64; ++tt) {
        int t = wp * 64 + tt;
        const float* row = base + (size_t)t * NU * D;
        float p = 0.f;
#pragma unroll
        for (int j = 0; j < 8; ++j) p += row[lane + 32 * j] * s_w[lane + 32 * j];
        for (int off = 16; off; off >>= 1) p += __shfl_down_sync(0xffffffffu, p, off);
        if (lane == 0) s_l[t] = p;     // ua_b omitted: softmax-invariant
    }
    __syncthreads();

    // softmax over L=512
    float m = -1e30f;
    for (int t = tid; t < L; t += 256) m = fmaxf(m, s_l[t]);
    for (int off = 16; off; off >>= 1) m = fmaxf(m, __shfl_xor_sync(0xffffffffu, m, off));
    if (lane == 0) s_red[wp] = m;
    __syncthreads();
    if (tid == 0) {
        float mm = s_red[0];
#pragma unroll
        for (int i = 1; i < 8; ++i) mm = fmaxf(mm, s_red[i]);
        s_red[16] = mm;
    }
    __syncthreads();
    m = s_red[16];
    float ssum = 0.f;
    for (int t = tid; t < L; t += 256) {
        float e = expf(s_l[t] - m);
        s_l[t] = e;
        ssum += e;
    }
    for (int off = 16; off; off >>= 1) ssum += __shfl_xor_sync(0xffffffffu, ssum, off);
    if (lane == 0) s_red[wp] = ssum;
    __syncthreads();
    if (tid == 0) {
        float ss = 0.f;
#pragma unroll
        for (int i = 0; i < 8; ++i) ss += s_red[i];
        s_red[17] = ss;
    }
    __syncthreads();
    const float inv = 1.f / s_red[17];

    // weighted sum over t (coalesced across hidden dim)
    float acc = 0.f;
#pragma unroll 8
    for (int t = 0; t < L; ++t) acc += s_l[t] * base[(size_t)t * NU * D + tid];
    g_utt[b * D + tid] = acc * inv;
}

// ---------------- sentence GRU step (T=1, h0=0) -> d_out ----------------
__global__ void __launch_bounds__(256, 1)
sent_kernel(const float* __restrict__ Wih, const float* __restrict__ bih,
            const float* __restrict__ bhh, float* __restrict__ out) {
    __shared__ float s_x[D];
    const int b = blockIdx.x, tid = threadIdx.x;
    s_x[tid] = g_utt[b * D + tid];
    __syncthreads();

    float xr = bih[tid], xz = bih[256 + tid], xn = bih[512 + tid];
    const float* wr = Wih + (size_t)tid * D;
    const float* wz = Wih + (size_t)(256 + tid) * D;
    const float* wn = Wih + (size_t)(512 + tid) * D;
#pragma unroll 4
    for (int k = 0; k < D; k += 4) {
        float4 a = *(const float4*)(wr + k);
        xr += a.x * s_x[k] + a.y * s_x[k + 1] + a.z * s_x[k + 2] + a.w * s_x[k + 3];
        float4 c = *(const float4*)(wz + k);
        xz += c.x * s_x[k] + c.y * s_x[k + 1] + c.z * s_x[k + 2] + c.w * s_x[k + 3];
        float4 e = *(const float4*)(wn + k);
        xn += e.x * s_x[k] + e.y * s_x[k + 1] + e.z * s_x[k + 2] + e.w * s_x[k + 3];
    }
    float r = sigmoidf_(xr + bhh[tid]);
    float z = sigmoidf_(xz + bhh[256 + tid]);
    float n = tanhf(xn + r * bhh[512 + tid]);
    out[b * D + tid] = (1.f - z) * n;   // + z*h0, h0 = 0
}

// ---------------- launch ----------------
extern "C" void kernel_launch(void* const* d_in, const int* in_sizes, int n_in,
                              void* d_out, int out_size) {
    const int*   tokens  = (const int*)  d_in[0];
    const float* embed   = (const float*)d_in[1];
    const float* wg_Wih  = (const float*)d_in[2];
    const float* wg_Whh  = (const float*)d_in[3];
    const float* wg_bih  = (const float*)d_in[4];
    const float* wg_bhh  = (const float*)d_in[5];
    const float* ua_w    = (const float*)d_in[6];
    // d_in[7] = ua_b   : softmax-invariant, unused
    const float* sg_Wih  = (const float*)d_in[8];
    // d_in[9] = sg_Whh : multiplied by h0 = 0, unused
    const float* sg_bih  = (const float*)d_in[10];
    const float* sg_bhh  = (const float*)d_in[11];
    // d_in[12], d_in[13] = da_w, da_b : softmax over T=1 is identity, unused
    float* out = (float*)d_out;

    cudaFuncSetAttribute(word_kernel, cudaFuncAttributeMaxDynamicSharedMemorySize,
                         WORD_SMEM_BYTES);

    reset_kernel<<<1, 32>>>();
    word_kernel<<<GB * GH, WT, WORD_SMEM_BYTES>>>(tokens, embed, wg_Wih, wg_Whh,
                                                  wg_bih, wg_bhh);
    pool_kernel<<<NU, 256>>>(ua_w);
    sent_kernel<<<NU, 256>>>(sg_Wih, sg_bih, sg_bhh, out);
}

// round 3
// speedup vs baseline: 1.0588x; 1.0588x over previous
#include <cuda_runtime.h>
#include <math.h>

#define D    256
#define L    512
#define NU   64
#define PAD  260        // padded SMEM row stride (floats): 1040B, 16B aligned, bank-skewed

// word kernel decomposition: 8 batch groups x 16 hidden slices = 128 CTAs
#define GB   8
#define UPG  8          // utterances per group
#define GH   16
#define HPS  16         // hidden units per slice
#define RPS  48         // gate rows per slice (3*HPS)
#define WT   384        // threads per CTA (RPS * UPG)

// ---------------- device scratch (static; no allocations) ----------------
__device__ float g_h_hist[(size_t)L * NU * D];   // word-GRU hidden history (33.5 MB)
__device__ float g_utt[NU * D];                  // utterance vectors after word attn-pool
__device__ int   g_flag[GB * GH];                // per-(group,slice) step flags

// ---------------- low-level helpers ----------------
__device__ __forceinline__ unsigned long long ffma2(unsigned long long a,
                                                    unsigned long long b,
                                                    unsigned long long c) {
    unsigned long long d;
    asm("fma.rn.f32x2 %0, %1, %2, %3;" : "=l"(d) : "l"(a), "l"(b), "l"(c));
    return d;
}
__device__ __forceinline__ float2 unpk2(unsigned long long v) {
    float2 r;
    asm("mov.b64 {%0, %1}, %2;" : "=f"(r.x), "=f"(r.y) : "l"(v));
    return r;
}
__device__ __forceinline__ int ld_acquire(const int* p) {
    int v;
    asm volatile("ld.acquire.gpu.b32 %0, [%1];" : "=r"(v) : "l"(p) : "memory");
    return v;
}
__device__ __forceinline__ void st_release(int* p, int v) {
    asm volatile("st.release.gpu.b32 [%0], %1;" :: "l"(p), "r"(v) : "memory");
}
__device__ __forceinline__ float sigmoidf_(float x) { return 1.f / (1.f + __expf(-x)); }

// gate row -> global weight row (gate order r, z, n)
__device__ __forceinline__ int gate_row(int i0, int lr) {
    return (lr < 16) ? (i0 + lr)
         : (lr < 32) ? (256 + i0 + (lr - 16))
                     : (512 + i0 + (lr - 32));
}

// dot over 256 floats via packed fp32x2 FMA; SMEM operands, 16B aligned
__device__ __forceinline__ float dot256(const float* __restrict__ w,
                                        const float* __restrict__ x) {
    const ulonglong2* W = (const ulonglong2*)w;
    const ulonglong2* X = (const ulonglong2*)x;
    unsigned long long a0 = 0ull, a1 = 0ull, a2 = 0ull, a3 = 0ull;
#pragma unroll 8
    for (int k = 0; k < 64; k += 2) {
        ulonglong2 w0 = W[k], w1 = W[k + 1];
        ulonglong2 x0 = X[k], x1 = X[k + 1];
        a0 = ffma2(w0.x, x0.x, a0);
        a1 = ffma2(w0.y, x0.y, a1);
        a2 = ffma2(w1.x, x1.x, a2);
        a3 = ffma2(w1.y, x1.y, a3);
    }
    float2 f0 = unpk2(a0), f1 = unpk2(a1), f2 = unpk2(a2), f3 = unpk2(a3);
    return ((f0.x + f0.y) + (f1.x + f1.y)) + ((f2.x + f2.y) + (f3.x + f3.y));
}

// ---------------- reset: zero flags each launch (graph-replay safe) ----------------
__global__ void reset_kernel() {
    if (threadIdx.x < GB * GH) g_flag[threadIdx.x] = 0;
}

// ---------------- word GRU persistent kernel ----------------
// SMEM (floats): wih[48][260]@0  whh[48][260]@12480  x[2][8][260]@24960
//                h[8][260]@29120 gih[384]@31200 ghh[384]@31584 bih[48]@31968 bhh[48]@32016
#define OFF_WIH 0
#define OFF_WHH 12480
#define OFF_X   24960
#define OFF_H   29120
#define OFF_GIH 31200
#define OFF_GHH 31584
#define OFF_BIH 31968
#define OFF_BHH 32016
#define WORD_SMEM_BYTES (32064 * 4)

__global__ void __launch_bounds__(WT, 1)
word_kernel(const int* __restrict__ tokens, const float* __restrict__ embed,
            const float* __restrict__ Wih, const float* __restrict__ Whh,
            const float* __restrict__ bih, const float* __restrict__ bhh) {
    extern __shared__ float sm[];
    float* s_wih = sm + OFF_WIH;
    float* s_whh = sm + OFF_WHH;
    float* s_x   = sm + OFF_X;
    float* s_h   = sm + OFF_H;
    float* s_gih = sm + OFF_GIH;
    float* s_ghh = sm + OFF_GHH;
    float* s_bih = sm + OFF_BIH;
    float* s_bhh = sm + OFF_BHH;

    const int g   = blockIdx.x >> 4;   // batch group
    const int sl  = blockIdx.x & 15;   // hidden slice
    const int i0  = sl * HPS;
    const int b0  = g * UPG;
    const int tid = threadIdx.x;
    const int u   = tid & 7;           // utterance within group
    const int lr  = tid >> 3;          // gate row within slice (0..47)
    const int wp  = tid >> 5;          // warp id (0..11)
    const int lane = tid & 31;
    const bool have2 = (tid < 128);

    // ---- prologue: resident weight slices + t=0 emb + zero h ----
    for (int idx = tid; idx < RPS * D; idx += WT) {
        int r = idx >> 8, k = idx & 255;
        int grow = gate_row(i0, r);
        s_wih[r * PAD + k] = Wih[grow * D + k];
        s_whh[r * PAD + k] = Whh[grow * D + k];
    }
    if (tid < RPS) {
        int grow = gate_row(i0, tid);
        s_bih[tid] = bih[grow];
        s_bhh[tid] = bhh[grow];
    }
    for (int idx = tid; idx < UPG * 64; idx += WT) {
        int uu = idx >> 6, k4 = idx & 63;
        int tok = tokens[(b0 + uu) * L + 0];
        ((float4*)(s_x + uu * PAD))[k4] = ((const float4*)(embed + (size_t)tok * D))[k4];
        ((float4*)(s_h + uu * PAD))[k4] = make_float4(0.f, 0.f, 0.f, 0.f);
    }
    __syncthreads();

    const float mybih = s_bih[lr];
    const float mybhh = s_bhh[lr];

    for (int t = 0; t < L; ++t) {
        const int buf = t & 1;

        // (A) issue embedding prefetch for t+1 (hidden behind ih dot)
        float4 pf0 = make_float4(0.f, 0.f, 0.f, 0.f);
        float4 pf1 = make_float4(0.f, 0.f, 0.f, 0.f);
        if (t + 1 < L) {
            int idx = tid, uu = idx >> 6, k4 = idx & 63;
            int tok = tokens[(b0 + uu) * L + (t + 1)];
            pf0 = ((const float4*)(embed + (size_t)tok * D))[k4];
            if (have2) {
                idx = tid + WT; uu = idx >> 6; k4 = idx & 63;
                tok = tokens[(b0 + uu) * L + (t + 1)];
                pf1 = ((const float4*)(embed + (size_t)tok * D))[k4];
            }
        }

        // (B) ih GEMV: needs only x_t — overlaps producers' h publication
        float aih = mybih + dot256(s_wih + lr * PAD, s_x + buf * 2080 + u * PAD);
        s_gih[tid] = aih;

        // (C) stage h_{t-1}: per-warp chunk fetch, per-slice flags
        if (t > 0) {
            const float* hsrc = g_h_hist + (size_t)(t - 1) * NU * D + (size_t)b0 * D;
            for (int s = wp; s < GH; s += 12) {
                const int* fp = &g_flag[g * GH + s];
                while (ld_acquire(fp) < t) { }
                int uu = lane >> 2, k4 = lane & 3;
                float4 v = *(const float4*)(hsrc + (size_t)uu * D + s * HPS + k4 * 4);
                *(float4*)(s_h + uu * PAD + s * HPS + k4 * 4) = v;
            }
        }
        __syncthreads();

        // (D) hh GEMV on staged h
        float ahh = mybhh + dot256(s_whh + lr * PAD, s_h + u * PAD);
        s_ghh[tid] = ahh;

        // park prefetched x_{t+1} into the other buffer (pre-sync)
        if (t + 1 < L) {
            int idx = tid, uu = idx >> 6, k4 = idx & 63;
            ((float4*)(s_x + (buf ^ 1) * 2080 + uu * PAD))[k4] = pf0;
            if (have2) {
                idx = tid + WT; uu = idx >> 6; k4 = idx & 63;
                ((float4*)(s_x + (buf ^ 1) * 2080 + uu * PAD))[k4] = pf1;
            }
        }
        __syncthreads();

        // (E) gates + hidden update + publish (coalesced STG: ii contiguous)
        if (tid < 128) {
            int ii = tid & 15, uu = tid >> 4;
            float xr = s_gih[ii * 8 + uu],        hr = s_ghh[ii * 8 + uu];
            float xz = s_gih[(16 + ii) * 8 + uu], hz = s_ghh[(16 + ii) * 8 + uu];
            float xn = s_gih[(32 + ii) * 8 + uu], hn = s_ghh[(32 + ii) * 8 + uu];
            float r = sigmoidf_(xr + hr);
            float z = sigmoidf_(xz + hz);
            float n = tanhf(xn + r * hn);
            float hprev = s_h[uu * PAD + i0 + ii];
            float hnew = (1.f - z) * n + z * hprev;
            g_h_hist[(size_t)t * NU * D + (size_t)(b0 + uu) * D + (i0 + ii)] = hnew;
        }
        __syncthreads();
        if (tid == 0) {
            __threadfence();                       // make h_t visible gpu-wide
            st_release(&g_flag[g * GH + sl], t + 1);
        }
    }
}

// ---------------- word-level attention pool: h_hist -> g_utt ----------------
__global__ void __launch_bounds__(256, 1)
pool_kernel(const float* __restrict__ ua_w) {
    __shared__ float s_w[D];
    __shared__ float s_l[L];
    __shared__ float s_red[32];
    const int b = blockIdx.x, tid = threadIdx.x;
    const int lane = tid & 31, wpp = tid >> 5;

    s_w[tid] = ua_w[tid];
    __syncthreads();

    const float* base = g_h_hist + (size_t)b * D;
    for (int tt = 0; tt < 64; ++tt) {
        int t = wpp * 64 + tt;
        const float* row = base + (size_t)t * NU * D;
        float p = 0.f;
#pragma unroll
        for (int j = 0; j < 8; ++j) p += row[lane + 32 * j] * s_w[lane + 32 * j];
        for (int off = 16; off; off >>= 1) p += __shfl_down_sync(0xffffffffu, p, off);
        if (lane == 0) s_l[t] = p;   // ua_b omitted: softmax-invariant
    }
    __syncthreads();

    float m = -1e30f;
    for (int t = tid; t < L; t += 256) m = fmaxf(m, s_l[t]);
    for (int off = 16; off; off >>= 1) m = fmaxf(m, __shfl_xor_sync(0xffffffffu, m, off));
    if (lane == 0) s_red[wpp] = m;
    __syncthreads();
    if (tid == 0) {
        float mm = s_red[0];
#pragma unroll
        for (int i = 1; i < 8; ++i) mm = fmaxf(mm, s_red[i]);
        s_red[16] = mm;
    }
    __syncthreads();
    m = s_red[16];
    float ssum = 0.f;
    for (int t = tid; t < L; t += 256) {
        float e = expf(s_l[t] - m);
        s_l[t] = e;
        ssum += e;
    }
    for (int off = 16; off; off >>= 1) ssum += __shfl_xor_sync(0xffffffffu, ssum, off);
    if (lane == 0) s_red[wpp] = ssum;
    __syncthreads();
    if (tid == 0) {
        float ss = 0.f;
#pragma unroll
        for (int i = 0; i < 8; ++i) ss += s_red[i];
        s_red[17] = ss;
    }
    __syncthreads();
    const float inv = 1.f / s_red[17];

    float acc = 0.f;
#pragma unroll 8
    for (int t = 0; t < L; ++t) acc += s_l[t] * base[(size_t)t * NU * D + tid];
    g_utt[b * D + tid] = acc * inv;
}

// ---------------- sentence GRU step (T=1, h0=0) -> d_out ----------------
__global__ void __launch_bounds__(256, 1)
sent_kernel(const float* __restrict__ Wih, const float* __restrict__ bih,
            const float* __restrict__ bhh, float* __restrict__ out) {
    __shared__ float s_x[D];
    const int b = blockIdx.x, tid = threadIdx.x;
    s_x[tid] = g_utt[b * D + tid];
    __syncthreads();

    float xr = bih[tid], xz = bih[256 + tid], xn = bih[512 + tid];
    const float* wr = Wih + (size_t)tid * D;
    const float* wz = Wih + (size_t)(256 + tid) * D;
    const float* wn = Wih + (size_t)(512 + tid) * D;
#pragma unroll 4
    for (int k = 0; k < D; k += 4) {
        float4 a = *(const float4*)(wr + k);
        xr += a.x * s_x[k] + a.y * s_x[k + 1] + a.z * s_x[k + 2] + a.w * s_x[k + 3];
        float4 c = *(const float4*)(wz + k);
        xz += c.x * s_x[k] + c.y * s_x[k + 1] + c.z * s_x[k + 2] + c.w * s_x[k + 3];
        float4 e = *(const float4*)(wn + k);
        xn += e.x * s_x[k] + e.y * s_x[k + 1] + e.z * s_x[k + 2] + e.w * s_x[k + 3];
    }
    float r = sigmoidf_(xr + bhh[tid]);
    float z = sigmoidf_(xz + bhh[256 + tid]);
    float n = tanhf(xn + r * bhh[512 + tid]);
    out[b * D + tid] = (1.f - z) * n;   // + z*h0, h0 = 0
}

// ---------------- launch ----------------
extern "C" void kernel_launch(void* const* d_in, const int* in_sizes, int n_in,
                              void* d_out, int out_size) {
    const int*   tokens  = (const int*)  d_in[0];
    const float* embed   = (const float*)d_in[1];
    const float* wg_Wih  = (const float*)d_in[2];
    const float* wg_Whh  = (const float*)d_in[3];
    const float* wg_bih  = (const float*)d_in[4];
    const float* wg_bhh  = (const float*)d_in[5];
    const float* ua_w    = (const float*)d_in[6];
    // d_in[7] = ua_b   : softmax-invariant, unused
    const float* sg_Wih  = (const float*)d_in[8];
    // d_in[9] = sg_Whh : multiplied by h0 = 0, unused
    const float* sg_bih  = (const float*)d_in[10];
    const float* sg_bhh  = (const float*)d_in[11];
    // d_in[12..13] = da_w, da_b : softmax over T=1 is identity, unused
    float* out = (float*)d_out;

    cudaFuncSetAttribute(word_kernel, cudaFuncAttributeMaxDynamicSharedMemorySize,
                         WORD_SMEM_BYTES);

    reset_kernel<<<1, 128>>>();
    word_kernel<<<GB * GH, WT, WORD_SMEM_BYTES>>>(tokens, embed, wg_Wih, wg_Whh,
                                                  wg_bih, wg_bhh);
    pool_kernel<<<NU, 256>>>(ua_w);
    sent_kernel<<<NU, 256>>>(sg_Wih, sg_bih, sg_bhh, out);
}